// round 11
// baseline (speedup 1.0000x reference)
#include <cuda_runtime.h>
#include <cuda_bf16.h>

// Problem constants (setup_inputs: 16 molecules x 512 atoms, cell = 20*I, cutoff = 5 -> 27 images)
#define NMOL 16
#define NAT  512
#define NIMG 27
#define TPB  256
#define ICH  8                    // i atoms per block (warp w owns atom il = w)
#define NIC  64                   // i-chunks per molecule
#define JCH  16                   // j's per thread (lane jc covers j in [jc*16, jc*16+16))
#define NBLK (NMOL * NIC)         // 1024 blocks
#define NBSUM (NMOL * NIMG * NIC) // 27648 run sums, order (m,k,ic) == global bucket order
#define ROWB (NIMG * TPB)         // 6912 byte counters per block

// hit <=> __fsqrt_rn(s) < 5.0f <=> s < (25.0f - 1ulp): sqrt_rn is correctly rounded
// & monotone; 0x41C7FFFF is the smallest float whose rounded sqrt reaches 5.0.
#define S_THRESH_BITS 0x41C7FFFFu

// Scratch (device globals; allocation forbidden)
__device__ int          g_bsum[NBSUM];
__device__ int          g_bsum_scan[NBSUM];
__device__ unsigned int g_mask[NBLK * TPB];    // per-thread 16-bit hit bitmask

// wrapped = fl( fl(c * fl(1/L)) * L ) -- bit-exact vs numpy (coords@inv_cell)@cell, diagonal cell
__device__ __forceinline__ float wrapf(float c, float inv, float L) {
    return __fmul_rn(__fmul_rn(c, inv), L);
}

// Min-image test, sqrt-free, bit-exact vs the reference image enumeration.
__device__ __forceinline__ bool pair_test(float dx, float dy, float dz,
                                          float hx, float hy, float hz,
                                          float Lx, float Ly, float Lz,
                                          int& k, float& fx, float& fy, float& fz)
{
    int ox = 0, oy = 0, oz = 0;
    fx = 0.0f; fy = 0.0f; fz = 0.0f;
    if (dx >  hx) { ox = -1; fx = -Lx; } else if (dx < -hx) { ox = 1; fx = Lx; }
    if (dy >  hy) { oy = -1; fy = -Ly; } else if (dy < -hy) { oy = 1; fy = Ly; }
    if (dz >  hz) { oz = -1; fz = -Lz; } else if (dz < -hz) { oz = 1; fz = Lz; }
    const float px = __fadd_rn(dx, fx), py = __fadd_rn(dy, fy), pz = __fadd_rn(dz, fz);
    const float s = __fadd_rn(__fadd_rn(__fmul_rn(px, px), __fmul_rn(py, py)),
                              __fmul_rn(pz, pz));
    k = (ox + 1) * 9 + (oy + 1) * 3 + (oz + 1);
    return s < __uint_as_float(S_THRESH_BITS);
}

// Compare-only image index for already-known hits.
__device__ __forceinline__ int image_k(float dx, float dy, float dz,
                                       float hx, float hy, float hz)
{
    const int ox = (dx > hx) ? -1 : ((dx < -hx) ? 1 : 0);
    const int oy = (dy > hy) ? -1 : ((dy < -hy) ? 1 : 0);
    const int oz = (dz > hz) ? -1 : ((dz < -hz) ? 1 : 0);
    return (ox + 1) * 9 + (oy + 1) * 3 + (oz + 1);
}

__device__ __forceinline__ int warp_incl_scan(int v) {
    const int lane = threadIdx.x & 31;
    #pragma unroll
    for (int d = 1; d < 32; d <<= 1) {
        int u = __shfl_up_sync(0xffffffffu, v, d);
        if (lane >= d) v += u;
    }
    return v;
}

// ---------------------------------------------------------------------------
// Kernel 1: geometry. Block = (m, ic); warp w owns atom i = ic*8+w (wi uniform
// per warp), lane = jc (16 j's). jj staggered by lane>>1 -> conflict-free LDS.
// Outputs per-thread hit bitmask + per-run sums. No persist of counts.
// ---------------------------------------------------------------------------
__global__ void __launch_bounds__(TPB) k_geom(const float* __restrict__ coords,
                                              const float* __restrict__ cell)
{
    const int m   = blockIdx.x >> 6;
    const int ic  = blockIdx.x & 63;
    const int tid = threadIdx.x;
    const int lane = tid & 31, w = tid >> 5;     // lane == jc, w == il

    __shared__ float swx[NAT], swy[NAT], swz[NAT];
    __shared__ unsigned char scnt[ROWB];

    const float Lx = cell[m * 9 + 0], Ly = cell[m * 9 + 4], Lz = cell[m * 9 + 8];
    const float invx = __fdiv_rn(1.0f, Lx), invy = __fdiv_rn(1.0f, Ly), invz = __fdiv_rn(1.0f, Lz);
    const float* cm = coords + (size_t)m * NAT * 3;
    for (int a = tid; a < NAT; a += TPB) {
        swx[a] = wrapf(cm[a * 3 + 0], invx, Lx);
        swy[a] = wrapf(cm[a * 3 + 1], invy, Ly);
        swz[a] = wrapf(cm[a * 3 + 2], invz, Lz);
    }
    for (int idx = tid; idx < ROWB / 4; idx += TPB)
        ((unsigned int*)scnt)[idx] = 0u;
    __syncthreads();

    const int i = ic * ICH + w;
    const float wx = swx[i], wy = swy[i], wz = swz[i];   // uniform per warp
    const float hx = 0.5f * Lx, hy = 0.5f * Ly, hz = 0.5f * Lz;
    const int j0 = lane * JCH;
    const int stag = lane >> 1;                  // bank-conflict-free stagger

    unsigned int mask = 0u;
    #pragma unroll 4
    for (int jj = 0; jj < JCH; jj++) {
        const int jja = (jj + stag) & 15;
        const int j = j0 + jja;
        if (j == i) continue;
        int k; float fx, fy, fz;
        if (pair_test(wx - swx[j], wy - swy[j], wz - swz[j],
                      hx, hy, hz, Lx, Ly, Lz, k, fx, fy, fz)) {
            scnt[k * TPB + tid]++;
            mask |= 1u << jja;                   // bit == true jj (j ascending)
        }
    }
    g_mask[blockIdx.x * TPB + tid] = mask;
    __syncthreads();

    // Per-run sums: warp w reduces rows k = w, w+8, ... via dp4a byte sums
    for (int k = w; k < NIMG; k += 8) {
        const unsigned int* row = (const unsigned int*)(scnt + k * TPB);
        int acc = __dp4a(row[lane], 0x01010101u, 0u)
                + __dp4a(row[lane + 32], 0x01010101u, 0u);
        #pragma unroll
        for (int d = 16; d; d >>= 1) acc += __shfl_xor_sync(0xffffffffu, acc, d);
        if (lane == 0) g_bsum[(m * NIMG + k) * NIC + ic] = acc;
    }
}

// ---------------------------------------------------------------------------
// Kernel 2: exclusive scan of the 27648 run sums (single block, 27/thread).
// ---------------------------------------------------------------------------
#define SEQ 27
__global__ void __launch_bounds__(1024) k_topscan()
{
    __shared__ int wsum[32];
    const int t = threadIdx.x, lane = t & 31, w = t >> 5;
    int vals[SEQ];
    int s = 0;
    #pragma unroll
    for (int q = 0; q < SEQ; q++) {
        const int v = g_bsum[t * SEQ + q];
        vals[q] = s; s += v;
    }
    int iv = warp_incl_scan(s);
    if (lane == 31) wsum[w] = iv;
    __syncthreads();
    if (w == 0) { int x = wsum[lane]; x = warp_incl_scan(x); wsum[lane] = x; }
    __syncthreads();
    const int pre = ((w > 0) ? wsum[w - 1] : 0) + (iv - s);
    #pragma unroll
    for (int q = 0; q < SEQ; q++)
        g_bsum_scan[t * SEQ + q] = pre + vals[q];
}

// ---------------------------------------------------------------------------
// Kernel 3: fill. Rebuilds byte counters from the hit mask (compare-only k),
// builds 216 warp-level prefixes (dp4a + width-8 shfl scan), then emits each
// hit at p = warppre[k][w] + lane_prefix + own_prior. No dense base table.
// Output layout (floats): [dist P | pf P | ps P | paircoord 3P | offsets 3P | oidx P]
// ---------------------------------------------------------------------------
__global__ void __launch_bounds__(TPB) k_fill(const float* __restrict__ coords,
                                              const float* __restrict__ cell,
                                              const int* __restrict__ real_atoms,
                                              const int* __restrict__ inv_ra,
                                              float* __restrict__ out, int P)
{
    const int m   = blockIdx.x >> 6;
    const int ic  = blockIdx.x & 63;
    const int tid = threadIdx.x;
    const int lane = tid & 31, w = tid >> 5;     // lane == jc, w == il

    __shared__ float swx[NAT], swy[NAT], swz[NAT];   // wrapped (mask path)
    __shared__ float scx[NAT], scy[NAT], scz[NAT];   // raw coordflat (output path)
    __shared__ float spf[NAT];                       // pair index as float
    __shared__ unsigned char scnt[ROWB];
    __shared__ int warppre[NIMG * 8];

    const float Lx = cell[m * 9 + 0], Ly = cell[m * 9 + 4], Lz = cell[m * 9 + 8];
    const float invx = __fdiv_rn(1.0f, Lx), invy = __fdiv_rn(1.0f, Ly), invz = __fdiv_rn(1.0f, Lz);
    const float* cm = coords + (size_t)m * NAT * 3;
    const int* ivr = inv_ra + m * NAT;

    for (int a = tid; a < NAT; a += TPB) {
        swx[a] = wrapf(cm[a * 3 + 0], invx, Lx);
        swy[a] = wrapf(cm[a * 3 + 1], invy, Ly);
        swz[a] = wrapf(cm[a * 3 + 2], invz, Lz);
        const int pf = ivr[a];
        const int rc = real_atoms[pf];
        scx[a] = coords[rc * 3 + 0];
        scy[a] = coords[rc * 3 + 1];
        scz[a] = coords[rc * 3 + 2];
        spf[a] = (float)pf;
    }
    for (int idx = tid; idx < ROWB / 4; idx += TPB)
        ((unsigned int*)scnt)[idx] = 0u;
    __syncthreads();

    const int i = ic * ICH + w;
    const float wx = swx[i], wy = swy[i], wz = swz[i];
    const float rcx = scx[i], rcy = scy[i], rcz = scz[i];
    const float fpf = spf[i];
    const float hx = 0.5f * Lx, hy = 0.5f * Ly, hz = 0.5f * Lz;
    const int j0 = lane * JCH;

    const unsigned int hitmask = g_mask[blockIdx.x * TPB + tid];

    // Walk 1: rebuild byte counters (compare-only k; avg ~2 hits/thread)
    {
        unsigned int msk = hitmask;
        while (msk) {
            const int jj = __ffs((int)msk) - 1;
            msk &= msk - 1;
            const int j = j0 + jj;
            const int k = image_k(wx - swx[j], wy - swy[j], wz - swz[j], hx, hy, hz);
            scnt[k * TPB + tid]++;
        }
    }
    __syncthreads();

    // Warp-level prefixes: thread t < 224 handles (k = t>>3, w8 = t&7);
    // dp4a row-warp totals + width-8 segmented exclusive scan + run base.
    if (tid < 224) {
        const int k = tid >> 3, w8 = tid & 7;
        int tot = 0;
        if (k < NIMG) {
            const unsigned int* row = (const unsigned int*)(scnt + k * TPB) + w8 * 8;
            #pragma unroll
            for (int q = 0; q < 8; q++) tot += __dp4a(row[q], 0x01010101u, 0u);
        }
        int pre = tot;
        #pragma unroll
        for (int d = 1; d < 8; d <<= 1) {
            int u = __shfl_up_sync(0xffffffffu, pre, d, 8);
            if ((tid & 7) >= d) pre += u;
        }
        if (k < NIMG)
            warppre[tid] = (pre - tot) + g_bsum_scan[(m * NIMG + k) * NIC + ic];
    }
    __syncthreads();

    // Walk 2: emit hits (ascending j per thread preserves reference order)
    unsigned int msk = hitmask;
    while (msk) {
        const int jj = __ffs((int)msk) - 1;
        msk &= msk - 1;
        const int j = j0 + jj;
        int k; float fx, fy, fz;
        pair_test(wx - swx[j], wy - swy[j], wz - swz[j],
                  hx, hy, hz, Lx, Ly, Lz, k, fx, fy, fz);   // guaranteed hit; need k, f*

        // own_prior: earlier own hits with same image k
        int own = 0;
        unsigned int pm = hitmask & ((1u << jj) - 1u);
        while (pm) {
            const int jb = __ffs((int)pm) - 1;
            pm &= pm - 1;
            const int jp = j0 + jb;
            own += (image_k(wx - swx[jp], wy - swy[jp], wz - swz[jp], hx, hy, hz) == k);
        }

        // lane_prefix: sum of row-k bytes for lanes < lane within this warp
        const unsigned int* r32 = (const unsigned int*)(scnt + k * TPB + w * 32);
        const int nw = lane >> 2;
        int lp = 0;
        #pragma unroll
        for (int q = 0; q < 8; q++)
            if (q < nw) lp += __dp4a(r32[q], 0x01010101u, 0u);
        const unsigned int shift = (lane & 3) * 8;
        lp += __dp4a(r32[nw] & ((1u << shift) - 1u), 0x01010101u, 0u);

        const int p = warppre[k * 8 + w] + lp + own;

        const float qx = __fadd_rn(rcx - scx[j], fx);
        const float qy = __fadd_rn(rcy - scy[j], fy);
        const float qz = __fadd_rn(rcz - scz[j], fz);
        const float s2 = __fadd_rn(__fadd_rn(__fmul_rn(qx, qx), __fmul_rn(qy, qy)),
                                   __fmul_rn(qz, qz));
        const int ox = k / 9 - 1, oy = (k / 3) % 3 - 1, oz = k % 3 - 1;

        out[p]                 = __fsqrt_rn(s2);    // distflat2 (sqrt only on hits)
        out[P + p]             = fpf;               // pair_first
        out[2 * P + p]         = spf[j];            // pair_second
        out[3 * P + 3 * p + 0] = qx;                // paircoord
        out[3 * P + 3 * p + 1] = qy;
        out[3 * P + 3 * p + 2] = qz;
        out[6 * P + 3 * p + 0] = (float)ox;         // offsets
        out[6 * P + 3 * p + 1] = (float)oy;
        out[6 * P + 3 * p + 2] = (float)oz;
        out[9 * P + p]         = (float)k;          // offset_index (n_images == 1)
    }
}

extern "C" void kernel_launch(void* const* d_in, const int* in_sizes, int n_in,
                              void* d_out, int out_size)
{
    const float* coords     = (const float*)d_in[0];
    const int*   real_atoms = (const int*)  d_in[2];
    const int*   inv_ra     = (const int*)  d_in[3];
    const float* cell       = (const float*)d_in[4];
    float* out = (float*)d_out;

    const int P = out_size / 10;

    k_geom   <<<NBLK, TPB>>>(coords, cell);
    k_topscan<<<1, 1024>>>();
    k_fill   <<<NBLK, TPB>>>(coords, cell, real_atoms, inv_ra, out, P);
}

// round 12
// speedup vs baseline: 1.1730x; 1.1730x over previous
#include <cuda_runtime.h>
#include <cuda_bf16.h>

// Problem constants (setup_inputs: 16 molecules x 512 atoms, cell = 20*I, cutoff = 5 -> 27 images)
#define NMOL 16
#define NAT  512
#define NIMG 27
#define TPB  256
#define ICH  16                   // i atoms per block
#define NIC  32                   // i-chunks per molecule (NAT/ICH)
#define JCH  32                   // j's per thread (fits u32 hit bitmask)
#define NBLK (NMOL * NIC)         // 512 blocks
#define NBSUM (NMOL * NIMG * NIC) // 13824 run sums, order (m,k,ic) == global bucket order
#define ROWB (NIMG * TPB)         // 6912 per-thread buckets per block

// hit <=> __fsqrt_rn(s) < 5.0f <=> s < (25.0f - 1ulp).  sqrt_rn is correctly rounded
// and monotone; s* = 0x41C7FFFF is the smallest float whose true sqrt
// (4.99999980926...) exceeds the rounding midpoint below 5.0 (4.99999976158...),
// so sqrt_rn(s*) == 5.0 while the next float down rounds below 5.0.
#define S_THRESH_BITS 0x41C7FFFFu

// Scratch (device globals; allocation forbidden)
__device__ int           g_bsum[NBSUM];
__device__ int           g_bsum_scan[NBSUM];
__device__ unsigned int  g_mask[NBLK * TPB];          // 512 KB: per-thread hit bitmask
__device__ unsigned char g_scnt[NBLK * ROWB];         // 3.5 MB: per-thread per-image counts

// wrapped = fl( fl(c * fl(1/L)) * L ) -- bit-exact vs numpy (coords@inv_cell)@cell, diagonal cell
__device__ __forceinline__ float wrapf(float c, float inv, float L) {
    return __fmul_rn(__fmul_rn(c, inv), L);
}

// Min-image membership test, sqrt-free, bit-exact vs the reference image enumeration
// (box > 2*cutoff => at most one image qualifies per ordered pair).
__device__ __forceinline__ bool pair_test(float dx, float dy, float dz,
                                          float hx, float hy, float hz,
                                          float Lx, float Ly, float Lz,
                                          int& k, float& fx, float& fy, float& fz)
{
    int ox = 0, oy = 0, oz = 0;
    fx = 0.0f; fy = 0.0f; fz = 0.0f;
    if (dx >  hx) { ox = -1; fx = -Lx; } else if (dx < -hx) { ox = 1; fx = Lx; }
    if (dy >  hy) { oy = -1; fy = -Ly; } else if (dy < -hy) { oy = 1; fy = Ly; }
    if (dz >  hz) { oz = -1; fz = -Lz; } else if (dz < -hz) { oz = 1; fz = Lz; }
    const float px = __fadd_rn(dx, fx), py = __fadd_rn(dy, fy), pz = __fadd_rn(dz, fz);
    const float s = __fadd_rn(__fadd_rn(__fmul_rn(px, px), __fmul_rn(py, py)),
                              __fmul_rn(pz, pz));
    k = (ox + 1) * 9 + (oy + 1) * 3 + (oz + 1);
    return s < __uint_as_float(S_THRESH_BITS);
}

__device__ __forceinline__ int warp_incl_scan(int v) {
    const int lane = threadIdx.x & 31;
    #pragma unroll
    for (int d = 1; d < 32; d <<= 1) {
        int u = __shfl_up_sync(0xffffffffu, v, d);
        if (lane >= d) v += u;
    }
    return v;
}

// ---------------------------------------------------------------------------
// Kernel 1: single geometry pass. Block = (m, ic); thread: il = tid&15 (atom),
// jc = tid>>4 (j-chunk). Half-warp shares jc -> swx[j] is a broadcast; jj is
// staggered by jc so the two half-warps hit different banks (conflict-free).
// Outputs: per-thread hit bitmask, per-thread per-image counts (scan position
// s = il*16+jc), per-run sums via dp4a reduction. No atomics anywhere.
// ---------------------------------------------------------------------------
__global__ void __launch_bounds__(TPB) k_geom(const float* __restrict__ coords,
                                              const float* __restrict__ cell)
{
    const int m   = blockIdx.x >> 5;
    const int ic  = blockIdx.x & 31;
    const int tid = threadIdx.x;
    const int il  = tid & 15, jc = tid >> 4;
    const int s   = il * 16 + jc;            // bucket scan position within run

    __shared__ float swx[NAT], swy[NAT], swz[NAT];
    __shared__ unsigned char scnt[ROWB];

    const float Lx = cell[m * 9 + 0], Ly = cell[m * 9 + 4], Lz = cell[m * 9 + 8];
    const float invx = __fdiv_rn(1.0f, Lx), invy = __fdiv_rn(1.0f, Ly), invz = __fdiv_rn(1.0f, Lz);
    const float* cm = coords + (size_t)m * NAT * 3;
    for (int a = tid; a < NAT; a += TPB) {
        swx[a] = wrapf(cm[a * 3 + 0], invx, Lx);
        swy[a] = wrapf(cm[a * 3 + 1], invy, Ly);
        swz[a] = wrapf(cm[a * 3 + 2], invz, Lz);
    }
    for (int idx = tid; idx < ROWB / 4; idx += TPB)
        ((unsigned int*)scnt)[idx] = 0u;
    __syncthreads();

    const int i = ic * ICH + il;
    const float wx = swx[i], wy = swy[i], wz = swz[i];
    const float hx = 0.5f * Lx, hy = 0.5f * Ly, hz = 0.5f * Lz;
    const int j0 = jc * JCH;

    unsigned int mask = 0u;
    #pragma unroll 4
    for (int jj = 0; jj < JCH; jj++) {
        const int jja = (jj + jc) & 31;      // stagger: conflict-free across half-warps
        const int j = j0 + jja;
        if (j == i) continue;
        int k; float fx, fy, fz;
        if (pair_test(wx - swx[j], wy - swy[j], wz - swz[j],
                      hx, hy, hz, Lx, Ly, Lz, k, fx, fy, fz)) {
            scnt[k * TPB + s]++;             // exclusive per-thread slot
            mask |= 1u << jja;               // bit index == actual jj (j ascending order)
        }
    }
    g_mask[blockIdx.x * TPB + tid] = mask;
    __syncthreads();

    // Persist counts (coalesced u32) for the fill kernel
    {
        const unsigned int* sc32 = (const unsigned int*)scnt;
        unsigned int* g32 = (unsigned int*)(g_scnt + (size_t)blockIdx.x * ROWB);
        for (int idx = tid; idx < ROWB / 4; idx += TPB) g32[idx] = sc32[idx];
    }

    // Per-run sums: warp w reduces rows k = w, w+8, ... via dp4a byte sums
    const int lane = tid & 31, w = tid >> 5;
    for (int k = w; k < NIMG; k += 8) {
        const unsigned int* row = (const unsigned int*)(scnt + k * TPB);
        int acc = __dp4a(row[lane], 0x01010101u, 0u)
                + __dp4a(row[lane + 32], 0x01010101u, 0u);
        #pragma unroll
        for (int d = 16; d; d >>= 1) acc += __shfl_xor_sync(0xffffffffu, acc, d);
        if (lane == 0) g_bsum[(m * NIMG + k) * NIC + ic] = acc;
    }
}

// ---------------------------------------------------------------------------
// Kernel 2: exclusive scan of the 13824 run sums (single block).
// ---------------------------------------------------------------------------
#define SEQ 14
__global__ void __launch_bounds__(1024) k_topscan()
{
    __shared__ int wsum[32];
    const int t = threadIdx.x, lane = t & 31, w = t >> 5;
    int vals[SEQ];
    int s = 0;
    #pragma unroll
    for (int q = 0; q < SEQ; q++) {
        const int idx = t * SEQ + q;
        const int v = (idx < NBSUM) ? g_bsum[idx] : 0;
        vals[q] = s; s += v;
    }
    int iv = warp_incl_scan(s);
    if (lane == 31) wsum[w] = iv;
    __syncthreads();
    if (w == 0) { int x = wsum[lane]; x = warp_incl_scan(x); wsum[lane] = x; }
    __syncthreads();
    const int pre = ((w > 0) ? wsum[w - 1] : 0) + (iv - s);
    #pragma unroll
    for (int q = 0; q < SEQ; q++) {
        const int idx = t * SEQ + q;
        if (idx < NBSUM) g_bsum_scan[idx] = pre + vals[q];
    }
}

// ---------------------------------------------------------------------------
// Kernel 3: fill. Loads stored counts, builds exclusive bases with 8 parallel
// warp scans (1 barrier), then a single mask walk (avg ~2 hits/thread),
// recomputing the (sqrt-free) pair test just for hits; sqrt only on outputs.
// Output layout (floats): [dist P | pf P | ps P | paircoord 3P | offsets 3P | oidx P]
// ---------------------------------------------------------------------------
__global__ void __launch_bounds__(TPB) k_fill(const float* __restrict__ coords,
                                              const float* __restrict__ cell,
                                              const int* __restrict__ real_atoms,
                                              const int* __restrict__ inv_ra,
                                              float* __restrict__ out, int P)
{
    const int m   = blockIdx.x >> 5;
    const int ic  = blockIdx.x & 31;
    const int tid = threadIdx.x;
    const int il  = tid & 15, jc = tid >> 4;
    const int s   = il * 16 + jc;
    const int lane = tid & 31, w = tid >> 5;

    __shared__ float swx[NAT], swy[NAT], swz[NAT];   // wrapped (mask path)
    __shared__ float scx[NAT], scy[NAT], scz[NAT];   // raw coordflat (output path)
    __shared__ float spf[NAT];                       // inv_real_atoms as float
    __shared__ int   sbase[ROWB];

    const float Lx = cell[m * 9 + 0], Ly = cell[m * 9 + 4], Lz = cell[m * 9 + 8];
    const float invx = __fdiv_rn(1.0f, Lx), invy = __fdiv_rn(1.0f, Ly), invz = __fdiv_rn(1.0f, Lz);
    const float* cm = coords + (size_t)m * NAT * 3;
    const int* ivr = inv_ra + m * NAT;

    for (int a = tid; a < NAT; a += TPB) {
        swx[a] = wrapf(cm[a * 3 + 0], invx, Lx);
        swy[a] = wrapf(cm[a * 3 + 1], invy, Ly);
        swz[a] = wrapf(cm[a * 3 + 2], invz, Lz);
        const int pf = ivr[a];
        const int rc = real_atoms[pf];
        scx[a] = coords[rc * 3 + 0];
        scy[a] = coords[rc * 3 + 1];
        scz[a] = coords[rc * 3 + 2];
        spf[a] = (float)pf;
    }

    // Exclusive bases: warp w scans rows k = w, w+8, ... (8 count-bytes/lane)
    {
        const unsigned char* gsc = g_scnt + (size_t)blockIdx.x * ROWB;
        for (int k = w; k < NIMG; k += 8) {
            const unsigned long long v =
                *(const unsigned long long*)(gsc + k * TPB + lane * 8);
            int b[8];
            int pre = 0;
            #pragma unroll
            for (int q = 0; q < 8; q++) {
                b[q] = pre;
                pre += (int)((v >> (8 * q)) & 0xFFull);
            }
            const int tot = pre;
            const int iv = warp_incl_scan(tot);
            const int ex = iv - tot;
            const int runbase = g_bsum_scan[(m * NIMG + k) * NIC + ic];
            #pragma unroll
            for (int q = 0; q < 8; q++)
                sbase[k * TPB + lane * 8 + q] = runbase + ex + b[q];
        }
    }
    __syncthreads();

    // Emit hits (ascending j per thread preserves reference np.nonzero order)
    const int i = ic * ICH + il;
    const float wx = swx[i], wy = swy[i], wz = swz[i];
    const float rcx = scx[i], rcy = scy[i], rcz = scz[i];
    const float fpf = spf[i];
    const float hx = 0.5f * Lx, hy = 0.5f * Ly, hz = 0.5f * Lz;
    const int j0 = jc * JCH;

    unsigned int msk = g_mask[blockIdx.x * TPB + tid];
    while (msk) {
        const int jj = __ffs((int)msk) - 1;
        msk &= msk - 1;
        const int j = j0 + jj;
        int k; float fx, fy, fz;
        pair_test(wx - swx[j], wy - swy[j], wz - swz[j],
                  hx, hy, hz, Lx, Ly, Lz, k, fx, fy, fz);   // guaranteed hit; need k, f*
        const int idx = k * TPB + s;
        const int p = sbase[idx];
        sbase[idx] = p + 1;                    // exclusive owner, no atomics

        const float qx = __fadd_rn(rcx - scx[j], fx);
        const float qy = __fadd_rn(rcy - scy[j], fy);
        const float qz = __fadd_rn(rcz - scz[j], fz);
        const float s2 = __fadd_rn(__fadd_rn(__fmul_rn(qx, qx), __fmul_rn(qy, qy)),
                                   __fmul_rn(qz, qz));
        const int ox = k / 9 - 1, oy = (k / 3) % 3 - 1, oz = k % 3 - 1;

        out[p]                 = __fsqrt_rn(s2);    // distflat2 (sqrt only on hits)
        out[P + p]             = fpf;               // pair_first
        out[2 * P + p]         = spf[j];            // pair_second
        out[3 * P + 3 * p + 0] = qx;                // paircoord
        out[3 * P + 3 * p + 1] = qy;
        out[3 * P + 3 * p + 2] = qz;
        out[6 * P + 3 * p + 0] = (float)ox;         // offsets
        out[6 * P + 3 * p + 1] = (float)oy;
        out[6 * P + 3 * p + 2] = (float)oz;
        out[9 * P + p]         = (float)k;          // offset_index (n_images == 1)
    }
}

extern "C" void kernel_launch(void* const* d_in, const int* in_sizes, int n_in,
                              void* d_out, int out_size)
{
    const float* coords     = (const float*)d_in[0];
    const int*   real_atoms = (const int*)  d_in[2];
    const int*   inv_ra     = (const int*)  d_in[3];
    const float* cell       = (const float*)d_in[4];
    float* out = (float*)d_out;

    const int P = out_size / 10;

    k_geom   <<<NBLK, TPB>>>(coords, cell);
    k_topscan<<<1, 1024>>>();
    k_fill   <<<NBLK, TPB>>>(coords, cell, real_atoms, inv_ra, out, P);
}